// round 1
// baseline (speedup 1.0000x reference)
#include <cuda_runtime.h>
#include <cuda_bf16.h>
#include <cstdint>

// GCMCGraphConv fused kernel (sm_100a)
//
// reference:
//   pa = sigmoid(feat @ prob_w.T)            [E,1]
//   rf = (feat @ review_w.T) * sigmoid(feat @ review_score_w.T)
//   m  = (weight[src]*pa + rf) * cj[src]
//   h  = segment_sum(m, dst) ; out = h * ci
// ci folds into the edge message: out[d] = sum_e m_e * ci[d].
//
// Strategy: 128-edge tiles. Per tile, the [128x64]@[64x64]^T GEMM runs on the
// tensor pipe via mma.sync.m16n8k8 tf32 with the 3xTF32 split (hi/lo) for
// ~fp32 accuracy. Gates computed per-edge from the same smem tile. Epilogue
// scatters with red.global.add.v2.f32 (ci/cj/pa gates applied in registers).

#define OUT_DIM 64
#define TILE_E 128
#define THREADS 256
#define FS 66   // feat smem row stride (floats) - even (f2-align) + conflict-light
#define WS 65   // review_w smem row stride

// smem layout (floats)
#define OFF_FEAT   0
#define OFF_WHI    (OFF_FEAT + TILE_E * FS)          // 8448
#define OFF_WLO    (OFF_WHI  + OUT_DIM * WS)         // +4160
#define OFF_PROBW  (OFF_WLO  + OUT_DIM * WS)         // +4160
#define OFF_RSW    (OFF_PROBW + OUT_DIM)
#define OFF_PA     (OFF_RSW  + OUT_DIM)
#define OFF_RS     (OFF_PA   + TILE_E)
#define OFF_CJCI   (OFF_RS   + TILE_E)
#define OFF_SRC    (OFF_CJCI + TILE_E)               // ints
#define OFF_DST    (OFF_SRC  + TILE_E)
#define SMEM_FLOATS (OFF_DST + TILE_E)
#define SMEM_BYTES  (SMEM_FLOATS * 4)

__device__ __forceinline__ unsigned f2tf32(float x) {
    unsigned r;
    asm("cvt.rna.tf32.f32 %0, %1;" : "=r"(r) : "f"(x));
    return r;
}

__device__ __forceinline__ void mma_tf32(float c[4], unsigned a0, unsigned a1,
                                         unsigned a2, unsigned a3,
                                         unsigned b0, unsigned b1) {
    asm volatile(
        "mma.sync.aligned.m16n8k8.row.col.f32.tf32.tf32.f32 "
        "{%0,%1,%2,%3}, {%4,%5,%6,%7}, {%8,%9}, {%0,%1,%2,%3};\n"
        : "+f"(c[0]), "+f"(c[1]), "+f"(c[2]), "+f"(c[3])
        : "r"(a0), "r"(a1), "r"(a2), "r"(a3), "r"(b0), "r"(b1));
}

__device__ __forceinline__ void red_add_v2(float* p, float x, float y) {
    asm volatile("red.global.add.v2.f32 [%0], {%1, %2};"
                 :: "l"(p), "f"(x), "f"(y) : "memory");
}

__device__ __forceinline__ float sigmoidf_(float x) {
    return 1.0f / (1.0f + __expf(-x));
}

__global__ void __launch_bounds__(THREADS)
gcmc_edge_kernel(const float* __restrict__ weight,      // [N_SRC,64]
                 const float* __restrict__ prob_w,      // [1,64]
                 const float* __restrict__ rsw,         // [1,64]
                 const float* __restrict__ review_w,    // [64,64]
                 const float* __restrict__ feat,        // [E,64]
                 const float* __restrict__ cj,          // [N_SRC,1]
                 const float* __restrict__ ci,          // [N_DST,1]
                 const int*   __restrict__ src_idx,     // [E]
                 const int*   __restrict__ dst_idx,     // [E]
                 float* __restrict__ out,               // [N_DST,64]
                 int E, int n_tiles)
{
    extern __shared__ float sm[];
    float* feat_s  = sm + OFF_FEAT;
    float* whi_s   = sm + OFF_WHI;
    float* wlo_s   = sm + OFF_WLO;
    float* probw_s = sm + OFF_PROBW;
    float* rsw_s   = sm + OFF_RSW;
    float* pa_s    = sm + OFF_PA;
    float* rs_s    = sm + OFF_RS;
    float* cjci_s  = sm + OFF_CJCI;
    int*   src_s   = (int*)(sm + OFF_SRC);
    int*   dst_s   = (int*)(sm + OFF_DST);

    const int tid  = threadIdx.x;
    const int lane = tid & 31;
    const int warp = tid >> 5;
    const int gid  = lane >> 2;   // 0..7
    const int tig  = lane & 3;    // 0..3

    // ---- one-time per block: split review_w into tf32 hi/lo in smem ----
    #pragma unroll
    for (int i = tid; i < OUT_DIM * OUT_DIM; i += THREADS) {
        float x = review_w[i];
        unsigned h = f2tf32(x);
        float hf = __uint_as_float(h);
        unsigned l = f2tf32(x - hf);
        int o = i >> 6, k = i & 63;
        whi_s[o * WS + k] = hf;
        wlo_s[o * WS + k] = __uint_as_float(l);
    }
    if (tid < OUT_DIM) {
        probw_s[tid] = prob_w[tid];
        rsw_s[tid]   = rsw[tid];
    }

    const float4* feat4 = (const float4*)feat;

    for (int tile = blockIdx.x; tile < n_tiles; tile += gridDim.x) {
        const int e_base = tile * TILE_E;

        // ---- load feat tile [128 x 64] coalesced (float4) ----
        #pragma unroll
        for (int i = 0; i < (TILE_E * OUT_DIM / 4) / THREADS; i++) {
            int g4 = tid + i * THREADS;           // 0..2047
            int r  = g4 >> 4;                     // row in tile
            int k4 = g4 & 15;                     // float4 within row
            float4 v;
            if (e_base + r < E) v = feat4[(size_t)e_base * 16 + g4];
            else                v = make_float4(0.f, 0.f, 0.f, 0.f);
            float* dstp = feat_s + r * FS + k4 * 4;
            dstp[0] = v.x; dstp[1] = v.y; dstp[2] = v.z; dstp[3] = v.w;
        }
        __syncthreads();

        // ---- gates: pa, rs, cj*ci per edge (threads 0..127) ----
        if (tid < TILE_E) {
            int e = e_base + tid;
            if (e < E) {
                int s = src_idx[e];
                int d = dst_idx[e];
                float d1 = 0.f, d2 = 0.f;
                const float* fr = feat_s + tid * FS;
                #pragma unroll
                for (int k = 0; k < OUT_DIM; k++) {
                    float f = fr[k];
                    d1 = fmaf(f, probw_s[k], d1);
                    d2 = fmaf(f, rsw_s[k], d2);
                }
                src_s[tid]  = s;
                dst_s[tid]  = d;
                pa_s[tid]   = sigmoidf_(d1);
                rs_s[tid]   = sigmoidf_(d2);
                cjci_s[tid] = cj[s] * ci[d];
            } else {
                src_s[tid] = 0; dst_s[tid] = 0;
                pa_s[tid] = 0.f; rs_s[tid] = 0.f; cjci_s[tid] = 0.f;
            }
        }

        // ---- GEMM: rf = feat_tile @ review_w^T via 3xTF32 mma ----
        // warp w owns rows [w*16, w*16+16); full N=64 via 8 n-tiles of 8.
        float c[8][4];
        #pragma unroll
        for (int n = 0; n < 8; n++) {
            c[n][0] = 0.f; c[n][1] = 0.f; c[n][2] = 0.f; c[n][3] = 0.f;
        }
        const float* As = feat_s + (warp * 16) * FS;
        #pragma unroll
        for (int ks = 0; ks < 8; ks++) {
            const int k0 = ks * 8;
            float x0 = As[(gid)     * FS + k0 + tig];
            float x1 = As[(gid + 8) * FS + k0 + tig];
            float x2 = As[(gid)     * FS + k0 + tig + 4];
            float x3 = As[(gid + 8) * FS + k0 + tig + 4];
            unsigned ah0 = f2tf32(x0), ah1 = f2tf32(x1),
                     ah2 = f2tf32(x2), ah3 = f2tf32(x3);
            unsigned al0 = f2tf32(x0 - __uint_as_float(ah0));
            unsigned al1 = f2tf32(x1 - __uint_as_float(ah1));
            unsigned al2 = f2tf32(x2 - __uint_as_float(ah2));
            unsigned al3 = f2tf32(x3 - __uint_as_float(ah3));
            #pragma unroll
            for (int n = 0; n < 8; n++) {
                const int ob = (n * 8 + gid) * WS + k0 + tig;
                unsigned bh0 = __float_as_uint(whi_s[ob]);
                unsigned bh1 = __float_as_uint(whi_s[ob + 4]);
                unsigned bl0 = __float_as_uint(wlo_s[ob]);
                unsigned bl1 = __float_as_uint(wlo_s[ob + 4]);
                mma_tf32(c[n], ah0, ah1, ah2, ah3, bh0, bh1);
                mma_tf32(c[n], ah0, ah1, ah2, ah3, bl0, bl1);
                mma_tf32(c[n], al0, al1, al2, al3, bh0, bh1);
            }
        }
        __syncthreads();  // gates visible; feat_s free for next iter

        // ---- epilogue: m = (weight[src]*pa + rf*rs) * cj*ci ; scatter ----
        const int r0 = warp * 16 + gid;
        const int r1 = r0 + 8;
        float pa0 = pa_s[r0], rsg0 = rs_s[r0], cc0 = cjci_s[r0];
        float pa1 = pa_s[r1], rsg1 = rs_s[r1], cc1 = cjci_s[r1];
        const float* w0 = weight + (size_t)src_s[r0] * OUT_DIM;
        const float* w1 = weight + (size_t)src_s[r1] * OUT_DIM;
        float* o0 = out + (size_t)dst_s[r0] * OUT_DIM;
        float* o1 = out + (size_t)dst_s[r1] * OUT_DIM;
        #pragma unroll
        for (int n = 0; n < 8; n++) {
            const int o = n * 8 + tig * 2;
            float2 wv0 = *(const float2*)(w0 + o);
            float m00 = (fmaf(wv0.x, pa0, c[n][0] * rsg0)) * cc0;
            float m01 = (fmaf(wv0.y, pa0, c[n][1] * rsg0)) * cc0;
            red_add_v2(o0 + o, m00, m01);
            float2 wv1 = *(const float2*)(w1 + o);
            float m10 = (fmaf(wv1.x, pa1, c[n][2] * rsg1)) * cc1;
            float m11 = (fmaf(wv1.y, pa1, c[n][3] * rsg1)) * cc1;
            red_add_v2(o1 + o, m10, m11);
        }
        // top-of-next-iter __syncthreads() (after feat load) protects pa_s
        // rewrites: every thread's epilogue reads complete before it passes
        // the next barrier.
    }
}

extern "C" void kernel_launch(void* const* d_in, const int* in_sizes, int n_in,
                              void* d_out, int out_size) {
    const float* weight   = (const float*)d_in[0];
    const float* prob_w   = (const float*)d_in[1];
    const float* rsw      = (const float*)d_in[2];
    const float* review_w = (const float*)d_in[3];
    const float* feat     = (const float*)d_in[4];
    const float* cj       = (const float*)d_in[5];
    const float* ci       = (const float*)d_in[6];
    const int*   src_idx  = (const int*)d_in[7];
    const int*   dst_idx  = (const int*)d_in[8];
    float* out = (float*)d_out;

    const int E = in_sizes[4] / OUT_DIM;
    const int n_tiles = (E + TILE_E - 1) / TILE_E;

    // zero the accumulator (d_out is poisoned before timing)
    cudaMemsetAsync(d_out, 0, (size_t)out_size * sizeof(float), 0);

    static int smem_set = 0;
    if (!smem_set) {
        cudaFuncSetAttribute(gcmc_edge_kernel,
                             cudaFuncAttributeMaxDynamicSharedMemorySize,
                             SMEM_BYTES);
        smem_set = 1;
    }

    int grid = n_tiles < 1776 ? n_tiles : 1776;
    gcmc_edge_kernel<<<grid, THREADS, SMEM_BYTES, 0>>>(
        weight, prob_w, rsw, review_w, feat, cj, ci, src_idx, dst_idx,
        out, E, n_tiles);
}

// round 2
// speedup vs baseline: 1.4546x; 1.4546x over previous
#include <cuda_runtime.h>
#include <cuda_bf16.h>
#include <cstdint>

// GCMCGraphConv fused kernel v2 (sm_100a)
//
//   pa = sigmoid(feat @ prob_w.T); rs = sigmoid(feat @ rsw.T)
//   rf = (feat @ review_w.T) * rs
//   out[d] += (weight[src]*pa + rf) * cj[src] * ci[d]
//
// v2 vs v1 (635us, L1tex 91.5% = wall):
//  - B operand (review_w hi/lo) prebuilt ONCE per block into fragment-major
//    smem float4 -> one conflict-free LDS.128 per (ntile,ks) instead of 4
//    conflicted scalar LDS; warp tile M=32 halves per-edge B traffic.
//  - gate matvecs folded into the GEMM as ntile 8 (cols: prob_w, rsw) ->
//    the conflicted 64-iter gate loop is gone; gates read via quad shuffle.
//  - mma k-slots remapped to memory k = 8ks+2tig+{0,1} (A and B agree) so
//    A fragment loads are 2 conflict-free LDS.64 per (mt,ks).

#define OUT_DIM 64
#define TILE_E  512
#define THREADS 512
#define FS      72      // feat smem row stride (floats): 8g+2t banks distinct
#define NT      9       // 8 rf n-tiles + 1 gate n-tile

struct Smem {
    float  feat[TILE_E * FS];      // 147456 B
    float4 bfrag[NT][8][32];       //  36864 B  (bh0,bh1,bl0,bl1)
    int    src[TILE_E];
    int    dst[TILE_E];
    float  cjci[TILE_E];
};                                  // total 190464 B

__device__ __forceinline__ unsigned f2tf32(float x) {
    unsigned r;
    asm("cvt.rna.tf32.f32 %0, %1;" : "=r"(r) : "f"(x));
    return r;
}

__device__ __forceinline__ void mma_tf32(float c[4], unsigned a0, unsigned a1,
                                         unsigned a2, unsigned a3,
                                         unsigned b0, unsigned b1) {
    asm volatile(
        "mma.sync.aligned.m16n8k8.row.col.f32.tf32.tf32.f32 "
        "{%0,%1,%2,%3}, {%4,%5,%6,%7}, {%8,%9}, {%0,%1,%2,%3};\n"
        : "+f"(c[0]), "+f"(c[1]), "+f"(c[2]), "+f"(c[3])
        : "r"(a0), "r"(a1), "r"(a2), "r"(a3), "r"(b0), "r"(b1));
}

__device__ __forceinline__ void red_add_v2(float* p, float x, float y) {
    asm volatile("red.global.add.v2.f32 [%0], {%1, %2};"
                 :: "l"(p), "f"(x), "f"(y) : "memory");
}

__device__ __forceinline__ float sigmoidf_(float x) {
    return 1.0f / (1.0f + __expf(-x));
}

__global__ void __launch_bounds__(THREADS, 1)
gcmc_kernel(const float* __restrict__ weight,      // [N_SRC,64]
            const float* __restrict__ prob_w,      // [64]
            const float* __restrict__ rsw,         // [64]
            const float* __restrict__ review_w,    // [64,64]
            const float* __restrict__ feat,        // [E,64]
            const float* __restrict__ cj,          // [N_SRC]
            const float* __restrict__ ci,          // [N_DST]
            const int*   __restrict__ src_idx,     // [E]
            const int*   __restrict__ dst_idx,     // [E]
            float* __restrict__ out,               // [N_DST,64]
            int E, int n_tiles)
{
    extern __shared__ char smraw[];
    Smem* sm = (Smem*)smraw;

    const int tid  = threadIdx.x;
    const int lane = tid & 31;
    const int warp = tid >> 5;
    const int gid  = lane >> 2;   // 0..7
    const int tig  = lane & 3;    // 0..3

    // ---- build B fragments once per block (hi/lo tf32 split, k-remapped) ----
    for (int i = tid; i < NT * 8 * 32; i += THREADS) {
        int l  = i & 31;
        int ks = (i >> 5) & 7;
        int nt = i >> 8;
        int g = l >> 2, t = l & 3;
        int k = 8 * ks + 2 * t;          // memory-k for slots (t, t+4)
        float w0 = 0.f, w1 = 0.f;
        if (nt < 8) {
            int o = nt * 8 + g;          // output dim for this lane
            w0 = review_w[o * 64 + k];
            w1 = review_w[o * 64 + k + 1];
        } else if (g == 0) {             // col 64 = pa dot
            w0 = prob_w[k]; w1 = prob_w[k + 1];
        } else if (g == 1) {             // col 65 = rs dot
            w0 = rsw[k];    w1 = rsw[k + 1];
        }
        unsigned h0 = f2tf32(w0), h1 = f2tf32(w1);
        unsigned l0 = f2tf32(w0 - __uint_as_float(h0));
        unsigned l1 = f2tf32(w1 - __uint_as_float(h1));
        sm->bfrag[nt][ks][l] = make_float4(
            __uint_as_float(h0), __uint_as_float(h1),
            __uint_as_float(l0), __uint_as_float(l1));
    }
    __syncthreads();

    const float4* feat4 = (const float4*)feat;
    const int rb = warp * 32;            // this warp's 32 rows

    for (int tile = blockIdx.x; tile < n_tiles; tile += gridDim.x) {
        const long e0 = (long)tile * TILE_E;

        // ---- stage feat tile [512 x 64] (coalesced float4 -> STS.128) ----
        #pragma unroll
        for (int i = 0; i < (TILE_E * OUT_DIM / 4) / THREADS; i++) {
            int g4 = tid + i * THREADS;      // 0..8191
            int r  = g4 >> 4;
            int k4 = g4 & 15;
            float4 v = make_float4(0.f, 0.f, 0.f, 0.f);
            if (e0 + r < E) v = feat4[(size_t)e0 * 16 + g4];
            *(float4*)&sm->feat[r * FS + k4 * 4] = v;
        }
        // ---- stage indices + cj*ci (1 edge per thread, coalesced idx) ----
        {
            long e = e0 + tid;
            int s = 0, d = 0; float cc = 0.f;
            if (e < E) {
                s = src_idx[e]; d = dst_idx[e];
                cc = cj[s] * ci[d];
            }
            sm->src[tid] = s; sm->dst[tid] = d; sm->cjci[tid] = cc;
        }
        __syncthreads();

        // ---- GEMM: c[mt][nt] = feat_tile(32 rows) @ [review_w|gates]^T ----
        float c[2][NT][4];
        #pragma unroll
        for (int mt = 0; mt < 2; mt++)
            #pragma unroll
            for (int nt = 0; nt < NT; nt++) {
                c[mt][nt][0] = 0.f; c[mt][nt][1] = 0.f;
                c[mt][nt][2] = 0.f; c[mt][nt][3] = 0.f;
            }

        #pragma unroll
        for (int ks = 0; ks < 8; ks++) {
            unsigned ah[2][4], al[2][4];
            #pragma unroll
            for (int mt = 0; mt < 2; mt++) {
                const int r0 = rb + mt * 16 + gid;
                // slots: a0/a2 = row r0 (k, k+1); a1/a3 = row r0+8
                float2 v0 = *(const float2*)&sm->feat[r0 * FS + 8 * ks + 2 * tig];
                float2 v1 = *(const float2*)&sm->feat[(r0 + 8) * FS + 8 * ks + 2 * tig];
                ah[mt][0] = f2tf32(v0.x); ah[mt][1] = f2tf32(v1.x);
                ah[mt][2] = f2tf32(v0.y); ah[mt][3] = f2tf32(v1.y);
                al[mt][0] = f2tf32(v0.x - __uint_as_float(ah[mt][0]));
                al[mt][1] = f2tf32(v1.x - __uint_as_float(ah[mt][1]));
                al[mt][2] = f2tf32(v0.y - __uint_as_float(ah[mt][2]));
                al[mt][3] = f2tf32(v1.y - __uint_as_float(ah[mt][3]));
            }
            #pragma unroll
            for (int nt = 0; nt < NT; nt++) {
                float4 b = sm->bfrag[nt][ks][lane];
                unsigned bh0 = __float_as_uint(b.x), bh1 = __float_as_uint(b.y);
                unsigned bl0 = __float_as_uint(b.z), bl1 = __float_as_uint(b.w);
                #pragma unroll
                for (int mt = 0; mt < 2; mt++) {
                    mma_tf32(c[mt][nt], ah[mt][0], ah[mt][1], ah[mt][2], ah[mt][3], bh0, bh1);
                    mma_tf32(c[mt][nt], ah[mt][0], ah[mt][1], ah[mt][2], ah[mt][3], bl0, bl1);
                    mma_tf32(c[mt][nt], al[mt][0], al[mt][1], al[mt][2], al[mt][3], bh0, bh1);
                }
            }
        }

        // ---- epilogue: gates via quad shuffle, gather weight, scatter red ----
        const int qsrc = lane & ~3;      // tig==0 lane of this quad
        #pragma unroll
        for (int mt = 0; mt < 2; mt++) {
            const int r0 = rb + mt * 16 + gid;
            const int r1 = r0 + 8;
            float pa0 = sigmoidf_(__shfl_sync(0xffffffffu, c[mt][8][0], qsrc));
            float rs0 = sigmoidf_(__shfl_sync(0xffffffffu, c[mt][8][1], qsrc));
            float pa1 = sigmoidf_(__shfl_sync(0xffffffffu, c[mt][8][2], qsrc));
            float rs1 = sigmoidf_(__shfl_sync(0xffffffffu, c[mt][8][3], qsrc));
            float cc0 = sm->cjci[r0], cc1 = sm->cjci[r1];
            const float* w0 = weight + (size_t)sm->src[r0] * OUT_DIM;
            const float* w1 = weight + (size_t)sm->src[r1] * OUT_DIM;
            float* o0 = out + (size_t)sm->dst[r0] * OUT_DIM;
            float* o1 = out + (size_t)sm->dst[r1] * OUT_DIM;
            #pragma unroll
            for (int nt = 0; nt < 8; nt++) {
                const int col = nt * 8 + 2 * tig;
                float2 wv0 = *(const float2*)(w0 + col);
                red_add_v2(o0 + col,
                           fmaf(wv0.x, pa0, c[mt][nt][0] * rs0) * cc0,
                           fmaf(wv0.y, pa0, c[mt][nt][1] * rs0) * cc0);
                float2 wv1 = *(const float2*)(w1 + col);
                red_add_v2(o1 + col,
                           fmaf(wv1.x, pa1, c[mt][nt][2] * rs1) * cc1,
                           fmaf(wv1.y, pa1, c[mt][nt][3] * rs1) * cc1);
            }
        }
        __syncthreads();   // protect smem (feat/idx) before next tile's stores
    }
}

extern "C" void kernel_launch(void* const* d_in, const int* in_sizes, int n_in,
                              void* d_out, int out_size) {
    const float* weight   = (const float*)d_in[0];
    const float* prob_w   = (const float*)d_in[1];
    const float* rsw      = (const float*)d_in[2];
    const float* review_w = (const float*)d_in[3];
    const float* feat     = (const float*)d_in[4];
    const float* cj       = (const float*)d_in[5];
    const float* ci       = (const float*)d_in[6];
    const int*   src_idx  = (const int*)d_in[7];
    const int*   dst_idx  = (const int*)d_in[8];
    float* out = (float*)d_out;

    const int E = in_sizes[4] / OUT_DIM;
    const int n_tiles = (E + TILE_E - 1) / TILE_E;

    cudaMemsetAsync(d_out, 0, (size_t)out_size * sizeof(float), 0);

    static int smem_set = 0;
    if (!smem_set) {
        cudaFuncSetAttribute(gcmc_kernel,
                             cudaFuncAttributeMaxDynamicSharedMemorySize,
                             (int)sizeof(Smem));
        smem_set = 1;
    }

    int grid = n_tiles < 148 ? n_tiles : 148;   // persistent, 1 block/SM
    gcmc_kernel<<<grid, THREADS, sizeof(Smem), 0>>>(
        weight, prob_w, rsw, review_w, feat, cj, ci, src_idx, dst_idx,
        out, E, n_tiles);
}

// round 3
// speedup vs baseline: 2.6057x; 1.7914x over previous
#include <cuda_runtime.h>
#include <cuda_fp16.h>
#include <cstdint>

// GCMCGraphConv fused kernel v3 (sm_100a)
//
//   pa = sigmoid(feat @ prob_w.T); rs = sigmoid(feat @ rsw.T)
//   rf = (feat @ review_w.T) * rs
//   out[d] += (weight[src]*pa + rf) * cj[src] * ci[d]
//
// v3 vs v2 (437us; occ 24.9%, issue 18.2% -> latency-bound):
//  - A operand loaded straight from GMEM into mma fragments (sector-perfect
//    LDG.64 per quad) -> feat smem staging + per-tile barrier GONE.
//  - fp16 m16n8k16 with 3-pass hi/lo split: half the mma count and half the
//    B smem wavefronts of the tf32 k8 version, same ~1e-6 accuracy.
//  - epilogue repacked via quad shuffles: weight gather LDG.128 and scatter
//    red.global.add.v4.f32 (half the LTS atomic ops).
//  - only 18KB smem (B fragments), 2 blocks/SM, no barriers in the loop.

#define OUT_DIM 64
#define THREADS 256
#define WARPS 8
#define TILE_E (WARPS * 32)   // 256 edges per block-iteration
#define NT 9                  // 8 rf n-tiles + 1 gate n-tile (cols 64,65)

struct SmemT { uint4 bfrag[NT][4][32]; };   // {bh_lo, bh_hi, bl_lo, bl_hi}

__device__ __forceinline__ void mma16816(float c[4],
    unsigned a0, unsigned a1, unsigned a2, unsigned a3,
    unsigned b0, unsigned b1)
{
    asm volatile(
      "mma.sync.aligned.m16n8k16.row.col.f32.f16.f16.f32 "
      "{%0,%1,%2,%3}, {%4,%5,%6,%7}, {%8,%9}, {%0,%1,%2,%3};\n"
      : "+f"(c[0]), "+f"(c[1]), "+f"(c[2]), "+f"(c[3])
      : "r"(a0), "r"(a1), "r"(a2), "r"(a3), "r"(b0), "r"(b1));
}

__device__ __forceinline__ void red_add_v4(float* p, float4 v) {
    asm volatile("red.global.add.v4.f32 [%0], {%1,%2,%3,%4};"
                 :: "l"(p), "f"(v.x), "f"(v.y), "f"(v.z), "f"(v.w) : "memory");
}

__device__ __forceinline__ unsigned packh2(float a, float b) {
    __half2 h = __floats2half2_rn(a, b);
    return *(unsigned*)&h;
}
__device__ __forceinline__ float2 h2f2(unsigned u) {
    __half2 h = *(__half2*)&u;
    return __half22float2(h);
}
// split float2 -> hi/lo half2 pair
__device__ __forceinline__ void split2(float2 p, unsigned& hi, unsigned& lo) {
    hi = packh2(p.x, p.y);
    float2 f = h2f2(hi);
    lo = packh2(p.x - f.x, p.y - f.y);
}

__global__ void __launch_bounds__(THREADS, 2)
gcmc_kernel(const float* __restrict__ weight,      // [N_SRC,64]
            const float* __restrict__ prob_w,      // [64]
            const float* __restrict__ rsw,         // [64]
            const float* __restrict__ review_w,    // [64,64]
            const float* __restrict__ feat,        // [E,64]
            const float* __restrict__ cj,          // [N_SRC]
            const float* __restrict__ ci,          // [N_DST]
            const int*   __restrict__ src_idx,     // [E]
            const int*   __restrict__ dst_idx,     // [E]
            float* __restrict__ out,               // [N_DST,64]
            int E, int n_tiles)
{
    __shared__ SmemT sm;

    const int tid  = threadIdx.x;
    const int lane = tid & 31;
    const int warp = tid >> 5;
    const int g    = lane >> 2;   // 0..7
    const int t    = lane & 3;    // 0..3

    // ---- build B fragments once per block (fp16 hi/lo, k16 slot layout) ----
    for (int i = tid; i < NT * 4 * 32; i += THREADS) {
        int l  = i & 31;
        int ks = (i >> 5) & 3;
        int nt = i >> 7;
        int gg = l >> 2, tt = l & 3;
        int k0 = 16 * ks + 2 * tt;         // slots {k0,k0+1} and {k0+8,k0+9}
        float w0 = 0.f, w1 = 0.f, w2 = 0.f, w3 = 0.f;
        if (nt < 8) {
            const float* W = review_w + (nt * 8 + gg) * OUT_DIM;
            w0 = W[k0]; w1 = W[k0 + 1]; w2 = W[k0 + 8]; w3 = W[k0 + 9];
        } else if (gg == 0) {   // gate col 64 = pa dot (prob_w)
            w0 = prob_w[k0]; w1 = prob_w[k0 + 1];
            w2 = prob_w[k0 + 8]; w3 = prob_w[k0 + 9];
        } else if (gg == 1) {   // gate col 65 = rs dot (review_score_w)
            w0 = rsw[k0]; w1 = rsw[k0 + 1];
            w2 = rsw[k0 + 8]; w3 = rsw[k0 + 9];
        }
        unsigned bh0 = packh2(w0, w1), bh1 = packh2(w2, w3);
        float2 f0 = h2f2(bh0), f1 = h2f2(bh1);
        unsigned bl0 = packh2(w0 - f0.x, w1 - f0.y);
        unsigned bl1 = packh2(w2 - f1.x, w3 - f1.y);
        sm.bfrag[nt][ks][l] = make_uint4(bh0, bh1, bl0, bl1);
    }
    __syncthreads();

    const int rb = warp * 32;           // warp's 32 rows within the tile
    const unsigned FULL = 0xffffffffu;
    const int q    = lane & ~3;         // quad leader lane
    const bool odd = t & 1;
    const int coff = (t & 2) << 1;      // 0 or 4

    for (int tile = blockIdx.x; tile < n_tiles; tile += gridDim.x) {
        const int e0 = tile * TILE_E;

        // ---- per-thread edge metadata (4 rows: mt x {g, g+8}) ----
        int srcA[2], srcB[2], dstA[2], dstB[2];
        float ccA[2], ccB[2];
        const float* fpA[2];
        const float* fpB[2];
        #pragma unroll
        for (int mt = 0; mt < 2; mt++) {
            int ea = e0 + rb + 16 * mt + g;
            int eb = ea + 8;
            bool va = ea < E, vb = eb < E;
            ea = va ? ea : E - 1;
            eb = vb ? eb : E - 1;
            fpA[mt] = feat + (size_t)ea * OUT_DIM;
            fpB[mt] = feat + (size_t)eb * OUT_DIM;
            int sa = src_idx[ea], sb = src_idx[eb];
            int da = dst_idx[ea], db = dst_idx[eb];
            srcA[mt] = sa; srcB[mt] = sb; dstA[mt] = da; dstB[mt] = db;
            ccA[mt] = va ? cj[sa] * ci[da] : 0.f;
            ccB[mt] = vb ? cj[sb] * ci[db] : 0.f;
        }

        // ---- GEMM: [32 rows/warp x 72 cols] = feat @ [review_w|gates]^T ----
        float c[2][NT][4];
        #pragma unroll
        for (int mt = 0; mt < 2; mt++)
            #pragma unroll
            for (int nt = 0; nt < NT; nt++) {
                c[mt][nt][0] = 0.f; c[mt][nt][1] = 0.f;
                c[mt][nt][2] = 0.f; c[mt][nt][3] = 0.f;
            }

        #pragma unroll
        for (int ks = 0; ks < 4; ks++) {
            unsigned ah[2][4], al[2][4];
            #pragma unroll
            for (int mt = 0; mt < 2; mt++) {
                const float* A0 = fpA[mt] + 16 * ks + 2 * t;
                const float* A1 = fpB[mt] + 16 * ks + 2 * t;
                float2 p00 = *(const float2*)A0;        // row g,   k {0,1}
                float2 p01 = *(const float2*)(A0 + 8);  // row g,   k {8,9}
                float2 p10 = *(const float2*)A1;        // row g+8, k {0,1}
                float2 p11 = *(const float2*)(A1 + 8);  // row g+8, k {8,9}
                split2(p00, ah[mt][0], al[mt][0]);
                split2(p10, ah[mt][1], al[mt][1]);
                split2(p01, ah[mt][2], al[mt][2]);
                split2(p11, ah[mt][3], al[mt][3]);
            }
            #pragma unroll
            for (int nt = 0; nt < NT; nt++) {
                uint4 b = sm.bfrag[nt][ks][lane];
                #pragma unroll
                for (int mt = 0; mt < 2; mt++) {
                    mma16816(c[mt][nt], ah[mt][0], ah[mt][1], ah[mt][2], ah[mt][3], b.x, b.y);
                    mma16816(c[mt][nt], ah[mt][0], ah[mt][1], ah[mt][2], ah[mt][3], b.z, b.w);
                    mma16816(c[mt][nt], al[mt][0], al[mt][1], al[mt][2], al[mt][3], b.x, b.y);
                }
            }
        }

        // ---- epilogue: gates, weight gather (LDG.128), scatter (red.v4) ----
        #pragma unroll
        for (int mt = 0; mt < 2; mt++) {
            float paA_ = __shfl_sync(FULL, c[mt][8][0], q);   // row g,   col 64
            float rsA_ = __shfl_sync(FULL, c[mt][8][1], q);   // row g,   col 65
            float paB_ = __shfl_sync(FULL, c[mt][8][2], q);   // row g+8, col 64
            float rsB_ = __shfl_sync(FULL, c[mt][8][3], q);   // row g+8, col 65
            float pa = odd ? paB_ : paA_;
            float rs = odd ? rsB_ : rsA_;
            pa = 1.f / (1.f + __expf(-pa));
            rs = 1.f / (1.f + __expf(-rs));
            float cc = odd ? ccB[mt] : ccA[mt];
            const float* wrow = weight + (size_t)(odd ? srcB[mt] : srcA[mt]) * OUT_DIM;
            float*       orow = out    + (size_t)(odd ? dstB[mt] : dstA[mt]) * OUT_DIM;
            #pragma unroll
            for (int nt = 0; nt < 8; nt++) {
                float x0 = __shfl_xor_sync(FULL, c[mt][nt][0], 1);
                float x1 = __shfl_xor_sync(FULL, c[mt][nt][1], 1);
                float x2 = __shfl_xor_sync(FULL, c[mt][nt][2], 1);
                float x3 = __shfl_xor_sync(FULL, c[mt][nt][3], 1);
                float r0, r1, r2, r3;
                if (!odd) { r0 = c[mt][nt][0]; r1 = c[mt][nt][1]; r2 = x0; r3 = x1; }
                else      { r0 = x2; r1 = x3; r2 = c[mt][nt][2]; r3 = c[mt][nt][3]; }
                const int col = nt * 8 + coff;
                float4 wv = *(const float4*)(wrow + col);
                float4 v;
                v.x = fmaf(wv.x, pa, r0 * rs) * cc;
                v.y = fmaf(wv.y, pa, r1 * rs) * cc;
                v.z = fmaf(wv.z, pa, r2 * rs) * cc;
                v.w = fmaf(wv.w, pa, r3 * rs) * cc;
                red_add_v4(orow + col, v);
            }
        }
    }
}

extern "C" void kernel_launch(void* const* d_in, const int* in_sizes, int n_in,
                              void* d_out, int out_size) {
    const float* weight   = (const float*)d_in[0];
    const float* prob_w   = (const float*)d_in[1];
    const float* rsw      = (const float*)d_in[2];
    const float* review_w = (const float*)d_in[3];
    const float* feat     = (const float*)d_in[4];
    const float* cj       = (const float*)d_in[5];
    const float* ci       = (const float*)d_in[6];
    const int*   src_idx  = (const int*)d_in[7];
    const int*   dst_idx  = (const int*)d_in[8];
    float* out = (float*)d_out;

    const int E = in_sizes[4] / OUT_DIM;
    const int n_tiles = (E + TILE_E - 1) / TILE_E;

    cudaMemsetAsync(d_out, 0, (size_t)out_size * sizeof(float), 0);

    int grid = n_tiles < 296 ? n_tiles : 296;   // 2 persistent blocks / SM
    gcmc_kernel<<<grid, THREADS, 0, 0>>>(
        weight, prob_w, rsw, review_w, feat, cj, ci, src_idx, dst_idx,
        out, E, n_tiles);
}